// round 8
// baseline (speedup 1.0000x reference)
#include <cuda_runtime.h>
#include <cuda_bf16.h>
#include <cstdint>

#define N_NODES 50000
#define N_EDGES 600000
#define D_FEAT  128
#define OUT_DIM 128

#define SCAN_BLK 512
#define N_SCAN_BLKS ((N_NODES + SCAN_BLK - 1) / SCAN_BLK)   // 98

#define BM  64                       // gemm rows per block
#define KQ  64                       // k-quarter
#define N_GEMM_BLKS ((N_NODES + BM - 1) / BM)   // 782
#define FUSED_SMEM ((KQ * OUT_DIM + BM * KQ) * 4)  // 32768 + 16384 = 49152

#define N_GATHER_BLKS ((N_NODES + 7) / 8)       // 6250 (8 nodes per block)
#define FUSED_GRID (N_GEMM_BLKS + N_GATHER_BLKS)  // 7032; every 9th block = gemm

// ---------------------------------------------------------------------------
// Scratch (static device globals)
// ---------------------------------------------------------------------------
__device__ int g_cnt_i [N_NODES];
__device__ int g_cursor[N_NODES];
__device__ int g_off   [N_NODES];
__device__ int g_btot  [N_SCAN_BLKS];
__device__ int g_eid   [N_EDGES];
__device__ __align__(16) float g_agg[N_NODES * D_FEAT];   // 25.6 MB

// ---------------------------------------------------------------------------
// Kernel 1: zero counters
// ---------------------------------------------------------------------------
__global__ void zero_counters_kernel() {
    int i = blockIdx.x * blockDim.x + threadIdx.x;
    if (i < N_NODES) { g_cnt_i[i] = 0; g_cursor[i] = 0; }
}

// ---------------------------------------------------------------------------
// Kernel 2: histogram of destination nodes
// ---------------------------------------------------------------------------
__global__ void count_kernel(const int* __restrict__ src_idx) {
    int e = blockIdx.x * blockDim.x + threadIdx.x;
    if (e < N_EDGES) atomicAdd(&g_cnt_i[src_idx[e]], 1);
}

// ---------------------------------------------------------------------------
// Kernel 3: per-block exclusive scan; block totals to g_btot
// ---------------------------------------------------------------------------
__global__ __launch_bounds__(SCAN_BLK)
void scan_partial_kernel() {
    __shared__ int sh[SCAN_BLK];
    const int tid = threadIdx.x;
    const int i   = blockIdx.x * SCAN_BLK + tid;
    const int v   = (i < N_NODES) ? g_cnt_i[i] : 0;
    sh[tid] = v;
    __syncthreads();
    #pragma unroll
    for (int d = 1; d < SCAN_BLK; d <<= 1) {
        int t = (tid >= d) ? sh[tid - d] : 0;
        __syncthreads();
        sh[tid] += t;
        __syncthreads();
    }
    if (i < N_NODES) g_off[i] = sh[tid] - v;
    if (tid == SCAN_BLK - 1) g_btot[blockIdx.x] = sh[tid];
}

// ---------------------------------------------------------------------------
// Inline 98-element exclusive prefix of g_btot into smem.
// ---------------------------------------------------------------------------
__device__ __forceinline__ void boff_scan(int* sb) {
    const int tid = threadIdx.x;
    int v = 0;
    if (tid < 128) {
        v = (tid < N_SCAN_BLKS) ? g_btot[tid] : 0;
        sb[tid] = v;
    }
    __syncthreads();
    #pragma unroll
    for (int d = 1; d < 128; d <<= 1) {
        int x = (tid < 128 && tid >= d) ? sb[tid - d] : 0;
        __syncthreads();
        if (tid < 128) sb[tid] += x;
        __syncthreads();
    }
    if (tid < 128) sb[tid] -= v;   // exclusive
    __syncthreads();
}

// ---------------------------------------------------------------------------
// Kernel 4: scatter edge ids into destination-sorted order (boff inlined)
// ---------------------------------------------------------------------------
__global__ __launch_bounds__(256)
void scatter_ids_kernel(const int* __restrict__ src_idx) {
    __shared__ int sb[128];
    boff_scan(sb);
    int e = blockIdx.x * blockDim.x + threadIdx.x;
    if (e < N_EDGES) {
        const int s = src_idx[e];
        const int pos = g_off[s] + sb[s >> 9] + atomicAdd(&g_cursor[s], 1);
        g_eid[pos] = e;
    }
}

// ---------------------------------------------------------------------------
// GEMM tile: 64 rows x 128 cols, K=128 in two K-quarters (smem 48KB).
// Thread t: cols j0=(t%32)*4, rows r0=(t/32)*8; packed fma.rn.f32x2.
// NOTE: callers must use a launch-bounds envelope of >= 128 regs/thread
// (256 threads, min 2 blocks). R7 used (256,4) = 64-reg cap -> accumulator
// spills -> +50us. Do not lower the reg budget.
// ---------------------------------------------------------------------------
__device__ __forceinline__ void gemm_tile(const float* __restrict__ xsrc,
                                          const float* __restrict__ Wq0,
                                          float*       __restrict__ out,
                                          int n0, float* sh, bool addout) {
    float* Wsh = sh;                // [KQ][OUT_DIM] 32KB
    float* Xsh = sh + KQ * OUT_DIM; // [BM][KQ]      16KB
    const int tid = threadIdx.x;

    const int j0 = (tid & 31) * 4;
    const int r0 = (tid >> 5) * 8;

    unsigned long long a01[8], a23[8];
    #pragma unroll
    for (int r = 0; r < 8; ++r) { a01[r] = 0ull; a23[r] = 0ull; }

    #pragma unroll
    for (int q = 0; q < 2; ++q) {
        if (q) __syncthreads();
        {
            const float4* W4 = reinterpret_cast<const float4*>(Wq0 + q * KQ * OUT_DIM);
            float4* Wsh4 = reinterpret_cast<float4*>(Wsh);
            #pragma unroll
            for (int i = tid; i < KQ * OUT_DIM / 4; i += 256) Wsh4[i] = W4[i];
        }
        {
            const float4* x4 = reinterpret_cast<const float4*>(xsrc);
            const float4  z  = make_float4(0.f, 0.f, 0.f, 0.f);
            #pragma unroll
            for (int i = tid; i < BM * (KQ / 4); i += 256) {
                const int r  = i / (KQ / 4);
                const int c4 = i % (KQ / 4);
                const int n  = n0 + r;
                float4 v = z;
                if (n < N_NODES)
                    v = x4[(size_t)n * (D_FEAT / 4) + q * (KQ / 4) + c4];
                reinterpret_cast<float4*>(&Xsh[r * KQ])[c4] = v;
            }
        }
        __syncthreads();

        #pragma unroll 2
        for (int k = 0; k < KQ; k += 2) {
            const unsigned long long wA0 =
                *reinterpret_cast<const unsigned long long*>(&Wsh[k * OUT_DIM + j0]);
            const unsigned long long wB0 =
                *reinterpret_cast<const unsigned long long*>(&Wsh[k * OUT_DIM + j0 + 2]);
            const unsigned long long wA1 =
                *reinterpret_cast<const unsigned long long*>(&Wsh[(k + 1) * OUT_DIM + j0]);
            const unsigned long long wB1 =
                *reinterpret_cast<const unsigned long long*>(&Wsh[(k + 1) * OUT_DIM + j0 + 2]);

            #pragma unroll
            for (int r = 0; r < 8; ++r) {
                const float2 x = *reinterpret_cast<const float2*>(&Xsh[(r0 + r) * KQ + k]);
                unsigned long long xx0, xx1;
                asm("mov.b64 %0, {%1, %1};" : "=l"(xx0) : "f"(x.x));
                asm("mov.b64 %0, {%1, %1};" : "=l"(xx1) : "f"(x.y));
                asm("fma.rn.f32x2 %0, %1, %2, %0;" : "+l"(a01[r]) : "l"(xx0), "l"(wA0));
                asm("fma.rn.f32x2 %0, %1, %2, %0;" : "+l"(a23[r]) : "l"(xx0), "l"(wB0));
                asm("fma.rn.f32x2 %0, %1, %2, %0;" : "+l"(a01[r]) : "l"(xx1), "l"(wA1));
                asm("fma.rn.f32x2 %0, %1, %2, %0;" : "+l"(a23[r]) : "l"(xx1), "l"(wB1));
            }
        }
    }

    #pragma unroll
    for (int r = 0; r < 8; ++r) {
        const int n = n0 + r0 + r;
        if (n < N_NODES) {
            float o0, o1, o2, o3;
            asm("mov.b64 {%0, %1}, %2;" : "=f"(o0), "=f"(o1) : "l"(a01[r]));
            asm("mov.b64 {%0, %1}, %2;" : "=f"(o2), "=f"(o3) : "l"(a23[r]));
            float4* po = reinterpret_cast<float4*>(&out[(size_t)n * OUT_DIM + j0]);
            if (addout) {
                const float4 prev = *po;
                *po = make_float4(prev.x + o0, prev.y + o1, prev.z + o2, prev.w + o3);
            } else {
                *po = make_float4(o0, o1, o2, o3);
            }
        }
    }
}

// ---------------------------------------------------------------------------
// Kernel 5 (fused): every 9th block = GEMM half0 (self_feat @ W[0:128] -> out),
// others = gather (one warp per node -> g_agg). DRAM-bound gather overlaps
// FMA-bound gemm within each wave. launch_bounds (256,2) = 128-reg budget.
// ---------------------------------------------------------------------------
__global__ __launch_bounds__(256, 2)
void fused_kernel(const float* __restrict__ self_feat,
                  const float* __restrict__ nbr_feat,
                  const float* __restrict__ W,
                  float*       __restrict__ out) {
    extern __shared__ float sh[];
    const int bid = blockIdx.x;

    if (bid % 9 == 0) {
        const int g = bid / 9;            // 0..781
        gemm_tile(self_feat, W, out, g * BM, sh, /*addout=*/false);
    } else {
        int* sb = reinterpret_cast<int*>(sh);
        boff_scan(sb);

        const int gid  = (bid / 9) * 8 + (bid % 9) - 1;   // 0..6249
        const int wid  = threadIdx.x >> 5;
        const int lane = threadIdx.x & 31;
        const int node = gid * 8 + wid;
        if (node >= N_NODES) return;

        const int base = g_off[node] + sb[node >> 9];
        const int deg  = g_cnt_i[node];

        const float4* nb4 = reinterpret_cast<const float4*>(nbr_feat);
        float4 acc = make_float4(0.f, 0.f, 0.f, 0.f);

        int i = 0;
        if (deg >= 2) {
            int e0 = g_eid[base];
            int e1 = g_eid[base + 1];
            for (; i + 4 <= deg; i += 2) {
                const int ne0 = g_eid[base + i + 2];
                const int ne1 = g_eid[base + i + 3];
                const float4 v0 = nb4[(size_t)e0 * (D_FEAT / 4) + lane];
                const float4 v1 = nb4[(size_t)e1 * (D_FEAT / 4) + lane];
                acc.x += v0.x + v1.x;  acc.y += v0.y + v1.y;
                acc.z += v0.z + v1.z;  acc.w += v0.w + v1.w;
                e0 = ne0; e1 = ne1;
            }
            const float4 v0 = nb4[(size_t)e0 * (D_FEAT / 4) + lane];
            const float4 v1 = nb4[(size_t)e1 * (D_FEAT / 4) + lane];
            acc.x += v0.x + v1.x;  acc.y += v0.y + v1.y;
            acc.z += v0.z + v1.z;  acc.w += v0.w + v1.w;
            i += 2;
        }
        for (; i < deg; ++i) {
            const int e = g_eid[base + i];
            const float4 v = nb4[(size_t)e * (D_FEAT / 4) + lane];
            acc.x += v.x; acc.y += v.y; acc.z += v.z; acc.w += v.w;
        }

        const float s = (deg > 0) ? (1.0f / (float)deg) : 0.0f;
        acc.x *= s; acc.y *= s; acc.z *= s; acc.w *= s;
        reinterpret_cast<float4*>(g_agg)[(size_t)node * (D_FEAT / 4) + lane] = acc;
    }
}

// ---------------------------------------------------------------------------
// Kernel 6: GEMM half1 — out += g_agg @ W[128:256]
// ---------------------------------------------------------------------------
__global__ __launch_bounds__(256, 2)
void gemm_half1_kernel(const float* __restrict__ W,
                       float*       __restrict__ out) {
    extern __shared__ float sh[];
    gemm_tile(g_agg, W + 128 * OUT_DIM, out, blockIdx.x * BM, sh, /*addout=*/true);
}

// ---------------------------------------------------------------------------
// Launch — 6 kernels
// ---------------------------------------------------------------------------
extern "C" void kernel_launch(void* const* d_in, const int* in_sizes, int n_in,
                              void* d_out, int out_size) {
    const float* self_feat = (const float*)d_in[0];
    const float* nbr_feat  = (const float*)d_in[1];
    const int*   src_idx   = (const int*)  d_in[2];
    const float* W         = (const float*)d_in[3];
    float*       out       = (float*)d_out;

    (void)in_sizes; (void)n_in; (void)out_size;

    const int nodes_blks = (N_NODES + 255) / 256;
    const int edges_blks = (N_EDGES + 255) / 256;

    zero_counters_kernel<<<nodes_blks, 256>>>();            // 1
    count_kernel<<<edges_blks, 256>>>(src_idx);             // 2
    scan_partial_kernel<<<N_SCAN_BLKS, SCAN_BLK>>>();       // 3
    scatter_ids_kernel<<<edges_blks, 256>>>(src_idx);       // 4

    cudaFuncSetAttribute(fused_kernel,
                         cudaFuncAttributeMaxDynamicSharedMemorySize, FUSED_SMEM);
    fused_kernel<<<FUSED_GRID, 256, FUSED_SMEM>>>(self_feat, nbr_feat, W, out);  // 5

    cudaFuncSetAttribute(gemm_half1_kernel,
                         cudaFuncAttributeMaxDynamicSharedMemorySize, FUSED_SMEM);
    gemm_half1_kernel<<<N_GEMM_BLKS, 256, FUSED_SMEM>>>(W, out);                 // 6
}

// round 9
// speedup vs baseline: 1.5054x; 1.5054x over previous
#include <cuda_runtime.h>
#include <cuda_bf16.h>
#include <cstdint>

#define N_NODES 50000
#define N_EDGES 600000
#define D_FEAT  128
#define OUT_DIM 128

#define SCAN_BLK 512
#define N_SCAN_BLKS ((N_NODES + SCAN_BLK - 1) / SCAN_BLK)   // 98

#define BM   64
#define TPB  256
#define KH   128                                    // K half
#define GEMM_SMEM ((KH * OUT_DIM + BM * KH) * 4)    // 65536 + 32768 = 98304 B
#define N_GEMM_BLKS ((N_NODES + BM - 1) / BM)       // 782

// ---------------------------------------------------------------------------
// Scratch (static device globals)
// ---------------------------------------------------------------------------
__device__ int g_cnt_i [N_NODES];
__device__ int g_cursor[N_NODES];
__device__ int g_off   [N_NODES];
__device__ int g_btot  [N_SCAN_BLKS];
__device__ int g_eid   [N_EDGES];
__device__ __align__(16) float g_agg[N_NODES * D_FEAT];   // 25.6 MB

// ---------------------------------------------------------------------------
// Kernel: zero counters
// ---------------------------------------------------------------------------
__global__ void zero_counters_kernel() {
    int i = blockIdx.x * blockDim.x + threadIdx.x;
    if (i < N_NODES) { g_cnt_i[i] = 0; g_cursor[i] = 0; }
}

// ---------------------------------------------------------------------------
// Kernel: histogram of destination nodes
// ---------------------------------------------------------------------------
__global__ void count_kernel(const int* __restrict__ src_idx) {
    int e = blockIdx.x * blockDim.x + threadIdx.x;
    if (e < N_EDGES) atomicAdd(&g_cnt_i[src_idx[e]], 1);
}

// ---------------------------------------------------------------------------
// Kernel: per-block exclusive scan; block totals to g_btot
// ---------------------------------------------------------------------------
__global__ __launch_bounds__(SCAN_BLK)
void scan_partial_kernel() {
    __shared__ int sh[SCAN_BLK];
    const int tid = threadIdx.x;
    const int i   = blockIdx.x * SCAN_BLK + tid;
    const int v   = (i < N_NODES) ? g_cnt_i[i] : 0;
    sh[tid] = v;
    __syncthreads();
    #pragma unroll
    for (int d = 1; d < SCAN_BLK; d <<= 1) {
        int t = (tid >= d) ? sh[tid - d] : 0;
        __syncthreads();
        sh[tid] += t;
        __syncthreads();
    }
    if (i < N_NODES) g_off[i] = sh[tid] - v;
    if (tid == SCAN_BLK - 1) g_btot[blockIdx.x] = sh[tid];
}

// ---------------------------------------------------------------------------
// Inline 98-element exclusive prefix of g_btot into smem (~200 cyc, replaces
// the 4.5us standalone scan_btot kernel). All threads join the syncs.
// ---------------------------------------------------------------------------
__device__ __forceinline__ void boff_scan(int* sb) {
    const int tid = threadIdx.x;
    int v = 0;
    if (tid < 128) {
        v = (tid < N_SCAN_BLKS) ? g_btot[tid] : 0;
        sb[tid] = v;
    }
    __syncthreads();
    #pragma unroll
    for (int d = 1; d < 128; d <<= 1) {
        int x = (tid < 128 && tid >= d) ? sb[tid - d] : 0;
        __syncthreads();
        if (tid < 128) sb[tid] += x;
        __syncthreads();
    }
    if (tid < 128) sb[tid] -= v;   // exclusive
    __syncthreads();
}

// ---------------------------------------------------------------------------
// Kernel: scatter edge ids into destination-sorted order (boff inlined)
// ---------------------------------------------------------------------------
__global__ __launch_bounds__(256)
void scatter_ids_kernel(const int* __restrict__ src_idx) {
    __shared__ int sb[128];
    boff_scan(sb);
    int e = blockIdx.x * blockDim.x + threadIdx.x;
    if (e < N_EDGES) {
        const int s = src_idx[e];
        const int pos = g_off[s] + sb[s >> 9] + atomicAdd(&g_cursor[s], 1);
        g_eid[pos] = e;
    }
}

// ---------------------------------------------------------------------------
// Kernel: gather-reduce. One warp per node; lane owns a float4 chunk.
// Lean envelope (low regs, 512B smem) so occupancy stays high -> DRAM BW.
// ---------------------------------------------------------------------------
__global__ __launch_bounds__(256)
void gather_kernel(const float* __restrict__ nbr_feat) {
    __shared__ int sb[128];
    boff_scan(sb);

    const int warp = (blockIdx.x * blockDim.x + threadIdx.x) >> 5;
    const int lane = threadIdx.x & 31;
    if (warp >= N_NODES) return;

    const int base = g_off[warp] + sb[warp >> 9];
    const int deg  = g_cnt_i[warp];

    const float4* nb4 = reinterpret_cast<const float4*>(nbr_feat);
    float4 acc = make_float4(0.f, 0.f, 0.f, 0.f);

    int i = 0;
    if (deg >= 2) {
        int e0 = g_eid[base];
        int e1 = g_eid[base + 1];
        for (; i + 4 <= deg; i += 2) {
            const int ne0 = g_eid[base + i + 2];      // prefetch next pair
            const int ne1 = g_eid[base + i + 3];
            const float4 v0 = nb4[(size_t)e0 * (D_FEAT / 4) + lane];
            const float4 v1 = nb4[(size_t)e1 * (D_FEAT / 4) + lane];
            acc.x += v0.x + v1.x;  acc.y += v0.y + v1.y;
            acc.z += v0.z + v1.z;  acc.w += v0.w + v1.w;
            e0 = ne0; e1 = ne1;
        }
        const float4 v0 = nb4[(size_t)e0 * (D_FEAT / 4) + lane];
        const float4 v1 = nb4[(size_t)e1 * (D_FEAT / 4) + lane];
        acc.x += v0.x + v1.x;  acc.y += v0.y + v1.y;
        acc.z += v0.z + v1.z;  acc.w += v0.w + v1.w;
        i += 2;
    }
    for (; i < deg; ++i) {
        const int e = g_eid[base + i];
        const float4 v = nb4[(size_t)e * (D_FEAT / 4) + lane];
        acc.x += v.x; acc.y += v.y; acc.z += v.z; acc.w += v.w;
    }

    const float s = (deg > 0) ? (1.0f / (float)deg) : 0.0f;
    acc.x *= s; acc.y *= s; acc.z *= s; acc.w *= s;
    reinterpret_cast<float4*>(g_agg)[(size_t)warp * (D_FEAT / 4) + lane] = acc;
}

// ---------------------------------------------------------------------------
// GEMM half tile (R6-proven): 64 rows x 128 cols, K=128 (one half of the
// concat), smem = 96KB, 2 CTAs/SM, packed fma.rn.f32x2.
// launch_bounds (256,2) = 128-reg budget — accumulators stay in registers.
// ---------------------------------------------------------------------------
__device__ __forceinline__ void gemm_half(const float* __restrict__ xsrc,
                                          const float* __restrict__ Wh,
                                          float*       __restrict__ out,
                                          int n0, float* sh, bool addout) {
    float* Wsh = sh;                 // [KH][OUT_DIM]
    float* Xsh = sh + KH * OUT_DIM;  // [BM][KH]
    const int tid = threadIdx.x;

    // Load W half (4096 float4)
    {
        const float4* W4 = reinterpret_cast<const float4*>(Wh);
        float4* Wsh4 = reinterpret_cast<float4*>(Wsh);
        #pragma unroll
        for (int i = tid; i < KH * OUT_DIM / 4; i += TPB) Wsh4[i] = W4[i];
    }
    // Load X half (rows n0..n0+63)
    {
        const float4* x4 = reinterpret_cast<const float4*>(xsrc);
        const float4  z  = make_float4(0.f, 0.f, 0.f, 0.f);
        #pragma unroll
        for (int i = tid; i < BM * (KH / 4); i += TPB) {
            const int r  = i / (KH / 4);
            const int c4 = i % (KH / 4);
            const int n  = n0 + r;
            float4 v = z;
            if (n < N_NODES) v = x4[(size_t)n * (D_FEAT / 4) + c4];
            reinterpret_cast<float4*>(&Xsh[r * KH])[c4] = v;
        }
    }
    __syncthreads();

    const int j0 = (tid & 31) * 4;
    const int r0 = (tid >> 5) * 8;

    unsigned long long a01[8], a23[8];
    #pragma unroll
    for (int r = 0; r < 8; ++r) { a01[r] = 0ull; a23[r] = 0ull; }

    #pragma unroll 2
    for (int k = 0; k < KH; k += 2) {
        const unsigned long long wA0 =
            *reinterpret_cast<const unsigned long long*>(&Wsh[k * OUT_DIM + j0]);
        const unsigned long long wB0 =
            *reinterpret_cast<const unsigned long long*>(&Wsh[k * OUT_DIM + j0 + 2]);
        const unsigned long long wA1 =
            *reinterpret_cast<const unsigned long long*>(&Wsh[(k + 1) * OUT_DIM + j0]);
        const unsigned long long wB1 =
            *reinterpret_cast<const unsigned long long*>(&Wsh[(k + 1) * OUT_DIM + j0 + 2]);

        #pragma unroll
        for (int r = 0; r < 8; ++r) {
            const float2 x = *reinterpret_cast<const float2*>(&Xsh[(r0 + r) * KH + k]);
            unsigned long long xx0, xx1;
            asm("mov.b64 %0, {%1, %1};" : "=l"(xx0) : "f"(x.x));
            asm("mov.b64 %0, {%1, %1};" : "=l"(xx1) : "f"(x.y));
            asm("fma.rn.f32x2 %0, %1, %2, %0;" : "+l"(a01[r]) : "l"(xx0), "l"(wA0));
            asm("fma.rn.f32x2 %0, %1, %2, %0;" : "+l"(a23[r]) : "l"(xx0), "l"(wB0));
            asm("fma.rn.f32x2 %0, %1, %2, %0;" : "+l"(a01[r]) : "l"(xx1), "l"(wA1));
            asm("fma.rn.f32x2 %0, %1, %2, %0;" : "+l"(a23[r]) : "l"(xx1), "l"(wB1));
        }
    }

    #pragma unroll
    for (int r = 0; r < 8; ++r) {
        const int n = n0 + r0 + r;
        if (n < N_NODES) {
            float o0, o1, o2, o3;
            asm("mov.b64 {%0, %1}, %2;" : "=f"(o0), "=f"(o1) : "l"(a01[r]));
            asm("mov.b64 {%0, %1}, %2;" : "=f"(o2), "=f"(o3) : "l"(a23[r]));
            float4* po = reinterpret_cast<float4*>(&out[(size_t)n * OUT_DIM + j0]);
            if (addout) {
                const float4 prev = *po;
                *po = make_float4(prev.x + o0, prev.y + o1, prev.z + o2, prev.w + o3);
            } else {
                *po = make_float4(o0, o1, o2, o3);
            }
        }
    }
}

// half0: out = self_feat @ W[0:128)   — independent of sort/gather; runs on s2
__global__ __launch_bounds__(TPB, 2)
void gemm_half0_kernel(const float* __restrict__ self_feat,
                       const float* __restrict__ W,
                       float*       __restrict__ out) {
    extern __shared__ float sh[];
    gemm_half(self_feat, W, out, blockIdx.x * BM, sh, /*addout=*/false);
}

// half1: out += g_agg @ W[128:256)
__global__ __launch_bounds__(TPB, 2)
void gemm_half1_kernel(const float* __restrict__ W,
                       float*       __restrict__ out) {
    extern __shared__ float sh[];
    gemm_half(g_agg, W + KH * OUT_DIM, out, blockIdx.x * BM, sh, /*addout=*/true);
}

// ---------------------------------------------------------------------------
// Launch. gemm_half0 forks onto a second stream (capture fork/join pattern)
// so its FMA work overlaps the DRAM-bound sort+gather chain. Each kernel
// keeps its own occupancy envelope — unlike the failed block-striping fusion.
// ---------------------------------------------------------------------------
extern "C" void kernel_launch(void* const* d_in, const int* in_sizes, int n_in,
                              void* d_out, int out_size) {
    const float* self_feat = (const float*)d_in[0];
    const float* nbr_feat  = (const float*)d_in[1];
    const int*   src_idx   = (const int*)  d_in[2];
    const float* W         = (const float*)d_in[3];
    float*       out       = (float*)d_out;

    (void)in_sizes; (void)n_in; (void)out_size;

    // Lazily-created host objects (no device memory). Work per call identical.
    static cudaStream_t s2 = nullptr;
    static cudaEvent_t ev_fork = nullptr, ev_join = nullptr;
    if (s2 == nullptr) {
        cudaStreamCreateWithFlags(&s2, cudaStreamNonBlocking);
        cudaEventCreateWithFlags(&ev_fork, cudaEventDisableTiming);
        cudaEventCreateWithFlags(&ev_join, cudaEventDisableTiming);
    }

    const int nodes_blks = (N_NODES + 255) / 256;
    const int edges_blks = (N_EDGES + 255) / 256;

    cudaFuncSetAttribute(gemm_half0_kernel,
                         cudaFuncAttributeMaxDynamicSharedMemorySize, GEMM_SMEM);
    cudaFuncSetAttribute(gemm_half1_kernel,
                         cudaFuncAttributeMaxDynamicSharedMemorySize, GEMM_SMEM);

    // Fork: gemm_half0 on s2 (independent of everything below)
    cudaEventRecord(ev_fork, 0);
    cudaStreamWaitEvent(s2, ev_fork, 0);
    gemm_half0_kernel<<<N_GEMM_BLKS, TPB, GEMM_SMEM, s2>>>(self_feat, W, out);
    cudaEventRecord(ev_join, s2);

    // Main chain on the capture stream
    zero_counters_kernel<<<nodes_blks, 256>>>();
    count_kernel<<<edges_blks, 256>>>(src_idx);
    scan_partial_kernel<<<N_SCAN_BLKS, SCAN_BLK>>>();
    scatter_ids_kernel<<<edges_blks, 256>>>(src_idx);
    gather_kernel<<<(N_NODES + 7) / 8, 256>>>(nbr_feat);

    // Join, then the dependent half
    cudaStreamWaitEvent(0, ev_join, 0);
    gemm_half1_kernel<<<N_GEMM_BLKS, TPB, GEMM_SMEM>>>(W, out);
}

// round 10
// speedup vs baseline: 1.6779x; 1.1146x over previous
#include <cuda_runtime.h>
#include <cuda_bf16.h>
#include <cstdint>

#define N_NODES 50000
#define N_EDGES 600000
#define D_FEAT  128
#define OUT_DIM 128
#define K_DIM   256

#define SCAN_BLK 512
#define N_SCAN_BLKS ((N_NODES + SCAN_BLK - 1) / SCAN_BLK)   // 98

// ---------------------------------------------------------------------------
// Scratch (static device globals)
// ---------------------------------------------------------------------------
__device__ int g_cnt_i [N_NODES];
__device__ int g_off   [N_NODES];
__device__ int g_btot  [N_SCAN_BLKS];
__device__ int g_rank  [N_EDGES];    // rank of edge within its segment
__device__ int g_eid   [N_EDGES];    // edge ids sorted by destination node
__device__ __align__(16) float g_agg[N_NODES * D_FEAT];   // 25.6 MB

// ---------------------------------------------------------------------------
// Kernel 1: zero counters (only g_cnt_i now — cursor eliminated by rank trick)
// ---------------------------------------------------------------------------
__global__ void zero_counters_kernel() {
    int i = blockIdx.x * blockDim.x + threadIdx.x;
    if (i < N_NODES) g_cnt_i[i] = 0;
}

// ---------------------------------------------------------------------------
// Kernel 2: histogram + per-edge rank in ONE atomic pass.
// ---------------------------------------------------------------------------
__global__ void count_rank_kernel(const int* __restrict__ src_idx) {
    int e = blockIdx.x * blockDim.x + threadIdx.x;
    if (e < N_EDGES) g_rank[e] = atomicAdd(&g_cnt_i[src_idx[e]], 1);
}

// ---------------------------------------------------------------------------
// Kernel 3: per-block exclusive scan; block totals to g_btot
// ---------------------------------------------------------------------------
__global__ __launch_bounds__(SCAN_BLK)
void scan_partial_kernel() {
    __shared__ int sh[SCAN_BLK];
    const int tid = threadIdx.x;
    const int i   = blockIdx.x * SCAN_BLK + tid;
    const int v   = (i < N_NODES) ? g_cnt_i[i] : 0;
    sh[tid] = v;
    __syncthreads();
    #pragma unroll
    for (int d = 1; d < SCAN_BLK; d <<= 1) {
        int t = (tid >= d) ? sh[tid - d] : 0;
        __syncthreads();
        sh[tid] += t;
        __syncthreads();
    }
    if (i < N_NODES) g_off[i] = sh[tid] - v;
    if (tid == SCAN_BLK - 1) g_btot[blockIdx.x] = sh[tid];
}

// ---------------------------------------------------------------------------
// Inline 98-element exclusive prefix of g_btot into smem (~200 cyc; replaces
// the 4.5us standalone scan_btot kernel). All threads must join the syncs.
// ---------------------------------------------------------------------------
__device__ __forceinline__ void boff_scan(int* sb) {
    const int tid = threadIdx.x;
    int v = 0;
    if (tid < 128) {
        v = (tid < N_SCAN_BLKS) ? g_btot[tid] : 0;
        sb[tid] = v;
    }
    __syncthreads();
    #pragma unroll
    for (int d = 1; d < 128; d <<= 1) {
        int x = (tid < 128 && tid >= d) ? sb[tid - d] : 0;
        __syncthreads();
        if (tid < 128) sb[tid] += x;
        __syncthreads();
    }
    if (tid < 128) sb[tid] -= v;   // exclusive
    __syncthreads();
}

// ---------------------------------------------------------------------------
// Kernel 4: scatter edge ids — ATOMIC-FREE now (rank precomputed).
// ---------------------------------------------------------------------------
__global__ __launch_bounds__(256)
void scatter_ids_kernel(const int* __restrict__ src_idx) {
    __shared__ int sb[128];
    boff_scan(sb);
    int e = blockIdx.x * blockDim.x + threadIdx.x;
    if (e < N_EDGES) {
        const int s = src_idx[e];
        g_eid[g_off[s] + sb[s >> 9] + g_rank[e]] = e;
    }
}

// ---------------------------------------------------------------------------
// Kernel 5: gather-reduce. One warp per node; lane owns a float4 chunk.
// 4 edge rows in flight per lane (ids prefetched ahead of the row loads).
// ---------------------------------------------------------------------------
__global__ __launch_bounds__(256)
void gather_kernel(const float* __restrict__ nbr_feat) {
    __shared__ int sb[128];
    boff_scan(sb);

    const int warp = (blockIdx.x * blockDim.x + threadIdx.x) >> 5;
    const int lane = threadIdx.x & 31;
    if (warp >= N_NODES) return;

    const int base = g_off[warp] + sb[warp >> 9];
    const int deg  = g_cnt_i[warp];

    const float4* nb4 = reinterpret_cast<const float4*>(nbr_feat);
    float4 acc = make_float4(0.f, 0.f, 0.f, 0.f);

    int i = 0;
    for (; i + 4 <= deg; i += 4) {   // 4 independent row loads in flight
        const int e0 = g_eid[base + i];
        const int e1 = g_eid[base + i + 1];
        const int e2 = g_eid[base + i + 2];
        const int e3 = g_eid[base + i + 3];
        const float4 v0 = nb4[(size_t)e0 * (D_FEAT / 4) + lane];
        const float4 v1 = nb4[(size_t)e1 * (D_FEAT / 4) + lane];
        const float4 v2 = nb4[(size_t)e2 * (D_FEAT / 4) + lane];
        const float4 v3 = nb4[(size_t)e3 * (D_FEAT / 4) + lane];
        acc.x += (v0.x + v1.x) + (v2.x + v3.x);
        acc.y += (v0.y + v1.y) + (v2.y + v3.y);
        acc.z += (v0.z + v1.z) + (v2.z + v3.z);
        acc.w += (v0.w + v1.w) + (v2.w + v3.w);
    }
    for (; i < deg; ++i) {
        const int e = g_eid[base + i];
        const float4 v = nb4[(size_t)e * (D_FEAT / 4) + lane];
        acc.x += v.x; acc.y += v.y; acc.z += v.z; acc.w += v.w;
    }

    const float s = (deg > 0) ? (1.0f / (float)deg) : 0.0f;
    acc.x *= s; acc.y *= s; acc.z *= s; acc.w *= s;
    reinterpret_cast<float4*>(g_agg)[(size_t)warp * (D_FEAT / 4) + lane] = acc;
}

// ---------------------------------------------------------------------------
// Kernel 6: fused concat + GEMM (R6-proven). K in two halves, smem 96KB,
// 2 CTAs/SM, packed fma.rn.f32x2. (256,2) = 128-reg budget (NEVER lower it:
// (256,4) spilled the accumulators in R7, +50us).
// ---------------------------------------------------------------------------
#define BM   64
#define TPB  256
#define KH   128
#define GEMM_SMEM ((KH * OUT_DIM + BM * KH) * 4)    // 98304 B

__global__ __launch_bounds__(TPB, 2)
void gemm_kernel(const float* __restrict__ self_feat,
                 const float* __restrict__ W,
                 float*       __restrict__ out) {
    extern __shared__ float sh[];
    float* Wsh = sh;                 // [KH][OUT_DIM]
    float* Xsh = sh + KH * OUT_DIM;  // [BM][KH]

    const int tid = threadIdx.x;
    const int n0  = blockIdx.x * BM;

    const int j0 = (tid & 31) * 4;
    const int r0 = (tid >> 5) * 8;

    unsigned long long a01[8], a23[8];
    #pragma unroll
    for (int r = 0; r < 8; ++r) { a01[r] = 0ull; a23[r] = 0ull; }

    #pragma unroll
    for (int half = 0; half < 2; ++half) {
        const float* xsrc = (half == 0) ? self_feat : g_agg;

        if (half == 1) __syncthreads();

        {
            const float4* W4 = reinterpret_cast<const float4*>(W + half * KH * OUT_DIM);
            float4* Wsh4 = reinterpret_cast<float4*>(Wsh);
            #pragma unroll
            for (int i = tid; i < KH * OUT_DIM / 4; i += TPB) Wsh4[i] = W4[i];
        }
        {
            const float4* x4 = reinterpret_cast<const float4*>(xsrc);
            const float4  z  = make_float4(0.f, 0.f, 0.f, 0.f);
            #pragma unroll
            for (int i = tid; i < BM * (KH / 4); i += TPB) {
                const int r  = i / (KH / 4);
                const int c4 = i % (KH / 4);
                const int n  = n0 + r;
                float4 v = z;
                if (n < N_NODES) v = x4[(size_t)n * (D_FEAT / 4) + c4];
                reinterpret_cast<float4*>(&Xsh[r * KH])[c4] = v;
            }
        }
        __syncthreads();

        #pragma unroll 2
        for (int k = 0; k < KH; k += 2) {
            const unsigned long long wA0 =
                *reinterpret_cast<const unsigned long long*>(&Wsh[k * OUT_DIM + j0]);
            const unsigned long long wB0 =
                *reinterpret_cast<const unsigned long long*>(&Wsh[k * OUT_DIM + j0 + 2]);
            const unsigned long long wA1 =
                *reinterpret_cast<const unsigned long long*>(&Wsh[(k + 1) * OUT_DIM + j0]);
            const unsigned long long wB1 =
                *reinterpret_cast<const unsigned long long*>(&Wsh[(k + 1) * OUT_DIM + j0 + 2]);

            #pragma unroll
            for (int r = 0; r < 8; ++r) {
                const float2 x = *reinterpret_cast<const float2*>(&Xsh[(r0 + r) * KH + k]);
                unsigned long long xx0, xx1;
                asm("mov.b64 %0, {%1, %1};" : "=l"(xx0) : "f"(x.x));
                asm("mov.b64 %0, {%1, %1};" : "=l"(xx1) : "f"(x.y));
                asm("fma.rn.f32x2 %0, %1, %2, %0;" : "+l"(a01[r]) : "l"(xx0), "l"(wA0));
                asm("fma.rn.f32x2 %0, %1, %2, %0;" : "+l"(a23[r]) : "l"(xx0), "l"(wB0));
                asm("fma.rn.f32x2 %0, %1, %2, %0;" : "+l"(a01[r]) : "l"(xx1), "l"(wA1));
                asm("fma.rn.f32x2 %0, %1, %2, %0;" : "+l"(a23[r]) : "l"(xx1), "l"(wB1));
            }
        }
    }

    #pragma unroll
    for (int r = 0; r < 8; ++r) {
        const int n = n0 + r0 + r;
        if (n < N_NODES) {
            float o0, o1, o2, o3;
            asm("mov.b64 {%0, %1}, %2;" : "=f"(o0), "=f"(o1) : "l"(a01[r]));
            asm("mov.b64 {%0, %1}, %2;" : "=f"(o2), "=f"(o3) : "l"(a23[r]));
            *reinterpret_cast<float4*>(&out[(size_t)n * OUT_DIM + j0]) =
                make_float4(o0, o1, o2, o3);
        }
    }
}

// ---------------------------------------------------------------------------
// Launch — 6 kernels, strictly serial (overlap attempts in R7-R9 all lost to
// SM-residency contention between the fat GEMM envelope and lean gather).
// ---------------------------------------------------------------------------
extern "C" void kernel_launch(void* const* d_in, const int* in_sizes, int n_in,
                              void* d_out, int out_size) {
    const float* self_feat = (const float*)d_in[0];
    const float* nbr_feat  = (const float*)d_in[1];
    const int*   src_idx   = (const int*)  d_in[2];
    const float* W         = (const float*)d_in[3];
    float*       out       = (float*)d_out;

    (void)in_sizes; (void)n_in; (void)out_size;

    const int nodes_blks = (N_NODES + 255) / 256;
    const int edges_blks = (N_EDGES + 255) / 256;

    zero_counters_kernel<<<nodes_blks, 256>>>();           // 1
    count_rank_kernel<<<edges_blks, 256>>>(src_idx);       // 2
    scan_partial_kernel<<<N_SCAN_BLKS, SCAN_BLK>>>();      // 3
    scatter_ids_kernel<<<edges_blks, 256>>>(src_idx);      // 4
    gather_kernel<<<(N_NODES + 7) / 8, 256>>>(nbr_feat);   // 5

    cudaFuncSetAttribute(gemm_kernel,
                         cudaFuncAttributeMaxDynamicSharedMemorySize, GEMM_SMEM);
    gemm_kernel<<<(N_NODES + BM - 1) / BM, TPB, GEMM_SMEM>>>(self_feat, W, out);  // 6
}